// round 2
// baseline (speedup 1.0000x reference)
#include <cuda_runtime.h>

// CornerProposal eval path on GB300 — R2: sector-aligned flat stores + fused anchor copy.
//
// Math (verified exact in R1, rel_err 5e-8):
//   anc_centers = floor(anc_bases[:,:,:2]) (integer-valued fp32)
//   grid_sample(align_corners=False) sample points land at integer - 0.5
//   => fx = fy = 0.5 exactly => pure 2x2 box average, no border cases:
//   out[b,n,c,i,j] = 0.25*(I[y-1,x-1]+I[y-1,x]+I[y,x-1]+I[y,x]),
//     y = cy+i-15, x = cx+j-15, all taps in [0,222] (in-bounds).
//
// R2 change: each task's 961 outputs are contiguous. Instead of 31 misaligned
// 31-float row stores (5 L2 sector-transactions per 124B row = 25% LTS slot
// waste), stage the task in smem and emit 31 sector-aligned 128B coalesced
// chunks (base rounded down to 8 floats, ragged ends predicated).
// Also folds the anchor-xy copy into the main kernel (kills a ~4us launch).

static constexpr int B = 8;
static constexpr int N = 600;
static constexpr int C = 32;
static constexpr int H = 256;
static constexpr int W = 256;
static constexpr int G = 31;                 // glimpse size
static constexpr int GG = G * G;             // 961
static constexpr int WARPS_PER_CTA = 8;
static constexpr int STAGE_STRIDE = GG + 7;  // 968, keeps warps bank-shifted

__global__ __launch_bounds__(WARPS_PER_CTA * 32)
void glimpse_kernel(const float* __restrict__ img,
                    const float* __restrict__ anc,
                    float* __restrict__ out,
                    float* __restrict__ out_xy)
{
    __shared__ float stage[WARPS_PER_CTA][STAGE_STRIDE];

    const int gwarp = (blockIdx.x * blockDim.x + threadIdx.x) >> 5;
    const int wslot = (threadIdx.x >> 5);
    const int lane  = threadIdx.x & 31;

    // warp -> (bn, c); C = 32 (power of two)
    const int c  = gwarp & (C - 1);
    const int bn = gwarp >> 5;
    if (bn >= B * N) return;

    // anchor center = floor of (xmin, ymin); exact integer in fp32
    const float ax = __ldg(anc + (size_t)bn * 4 + 0);
    const float ay = __ldg(anc + (size_t)bn * 4 + 1);

    // fused anchor-xy copy (replaces the separate copy kernel)
    if (c == 0 && lane < 2)
        out_xy[2 * bn + lane] = (lane == 0) ? ax : ay;

    const int cx = (int)floorf(ax);
    const int cy = (int)floorf(ay);
    const int b  = bn / N;

    // patch top-left: (cy-16, cx-16); 32 rows x 32 cols, guaranteed in-bounds
    const float* base = img + (((size_t)(b * C + c)) * H + (size_t)(cy - 16)) * W
                            + (cx - 16);

    // Load full 32x32 patch column for this lane — fully unrolled independent
    // LDGs (high MLP, mostly L2 hits since the 67MB image set fits in L2).
    float r[32];
    #pragma unroll
    for (int i = 0; i < 32; ++i)
        r[i] = __ldg(base + i * W + lane);

    // Compute: vertical pair sum per column, horizontal pair via shfl,
    // stage flat into smem: stage[wslot][i*31 + j], j = lane (0..30).
    #pragma unroll
    for (int i = 0; i < G; ++i) {
        const float s = r[i] + r[i + 1];
        const float t = s + __shfl_down_sync(0xffffffffu, s, 1);
        if (lane < G)
            stage[wslot][i * G + lane] = 0.25f * t;
    }
    __syncwarp();

    // Emit as sector-aligned coalesced 128B chunks.
    const size_t obase = ((size_t)bn * C + c) * (size_t)GG;  // flat element idx
    const int    off   = (int)(obase & 7);                   // 0..7
    float* __restrict__ oa = out + (obase - off);            // 32B-aligned

    // off + 961 <= 968 <= 31*32, so exactly 31 chunks cover the region.
    #pragma unroll
    for (int k = 0; k < 31; ++k) {
        const int rel = 32 * k + lane;
        if (rel >= off && rel < off + GG)
            oa[rel] = stage[wslot][rel - off];
    }
}

extern "C" void kernel_launch(void* const* d_in, const int* in_sizes, int n_in,
                              void* d_out, int out_size)
{
    const float* img = (const float*)d_in[0];   // [B, C, H, W] fp32
    const float* anc = (const float*)d_in[1];   // [B, N, 4]   fp32
    float* out = (float*)d_out;

    // rois first, anchors(:, :, :2) appended — derive tail offset from out_size
    float* out_xy = out + (out_size - B * N * 2);

    const int total_warps = B * N * C;          // 153600
    const int threads = WARPS_PER_CTA * 32;     // 256
    const int blocks = (total_warps + WARPS_PER_CTA - 1) / WARPS_PER_CTA;

    glimpse_kernel<<<blocks, threads>>>(img, anc, out, out_xy);

    (void)n_in; (void)in_sizes; (void)out_size;
}

// round 3
// speedup vs baseline: 1.2377x; 1.2377x over previous
#include <cuda_runtime.h>
#include <cstdint>

// CornerProposal eval path on GB300 — R3: TMA bulk stores, fused anchor copy.
//
// Math (exact, verified R1/R2 rel_err 5e-8): centers are integer-valued fp32,
// grid_sample(align_corners=False) => fx=fy=0.5 exactly => pure 2x2 box avg,
// all taps in-bounds.
//
// R3: R1's compute (lane=column, 32 front-batched LDGs, shfl for +1 col), but
// the 961 contiguous outputs are staged in smem (31 conflict-free STS) and
// emitted with cp.async.bulk smem->global: packed sectors into L2, no L1tex
// wavefronts for the store stream. Ragged <=3-float head/tail via STG.

static constexpr int B = 8;
static constexpr int N = 600;
static constexpr int C = 32;
static constexpr int H = 256;
static constexpr int W = 256;
static constexpr int G = 31;
static constexpr int GG = G * G;             // 961
static constexpr int WARPS_PER_CTA = 8;
static constexpr int STAGE_F = 968;          // 4 pad + 961, rounded to 16B mult

__global__ __launch_bounds__(WARPS_PER_CTA * 32)
void glimpse_kernel(const float* __restrict__ img,
                    const float* __restrict__ anc,
                    float* __restrict__ out,
                    float* __restrict__ out_xy)
{
    __shared__ __align__(16) float stage[WARPS_PER_CTA][STAGE_F];

    const int gwarp = (blockIdx.x * blockDim.x + threadIdx.x) >> 5;
    const int wslot = threadIdx.x >> 5;
    const int lane  = threadIdx.x & 31;

    const int c  = gwarp & (C - 1);
    const int bn = gwarp >> 5;
    if (bn >= B * N) return;

    const float ax = __ldg(anc + (size_t)bn * 4 + 0);
    const float ay = __ldg(anc + (size_t)bn * 4 + 1);

    // fused anchor-xy copy
    if (c == 0 && lane < 2)
        out_xy[2 * bn + lane] = (lane == 0) ? ax : ay;

    const int cx = (int)floorf(ax);
    const int cy = (int)floorf(ay);
    const int b  = bn / N;

    const float* base = img + (((size_t)(b * C + c)) * H + (size_t)(cy - 16)) * W
                            + (cx - 16);

    // full 32x32 patch, one float per lane per row; unrolled for MLP
    float r[32];
    #pragma unroll
    for (int i = 0; i < 32; ++i)
        r[i] = __ldg(base + i * W + lane);

    const size_t obase = ((size_t)bn * C + c) * (size_t)GG;  // flat elem index
    const int head = (int)((4 - (obase & 3)) & 3);           // elems to 16B align
    const int tail = (int)((obase + GG) & 3);
    const int sh   = 4 - head;  // element e lives at stage[sh + e]; e=head -> idx 4 (16B aligned)

    #pragma unroll
    for (int i = 0; i < G; ++i) {
        const float s = r[i] + r[i + 1];
        const float t = s + __shfl_down_sync(0xffffffffu, s, 1);
        if (lane < G)
            stage[wslot][sh + i * G + lane] = 0.25f * t;
    }
    __syncwarp();

    // ragged edges (<=3 floats each) straight to global
    if (lane < head) out[obase + lane] = stage[wslot][sh + lane];
    if (lane < tail) out[obase + GG - tail + lane] = stage[wslot][sh + GG - tail + lane];

    // packed interior via TMA bulk store (16B-aligned both sides, mult of 16B)
    if (lane == 0) {
        asm volatile("fence.proxy.async.shared::cta;" ::: "memory");
        const uint32_t saddr = (uint32_t)__cvta_generic_to_shared(&stage[wslot][4]);
        const int bytes = (GG - head - tail) * 4;
        const float* gptr = out + obase + head;
        asm volatile(
            "cp.async.bulk.global.shared::cta.bulk_group [%0], [%1], %2;"
            :: "l"(gptr), "r"(saddr), "r"(bytes) : "memory");
        asm volatile("cp.async.bulk.commit_group;" ::: "memory");
        // wait for smem reads only; global visibility is guaranteed at kernel end
        asm volatile("cp.async.bulk.wait_group.read 0;" ::: "memory");
    }
}

extern "C" void kernel_launch(void* const* d_in, const int* in_sizes, int n_in,
                              void* d_out, int out_size)
{
    const float* img = (const float*)d_in[0];   // [B, C, H, W] fp32
    const float* anc = (const float*)d_in[1];   // [B, N, 4]   fp32
    float* out = (float*)d_out;
    float* out_xy = out + (out_size - B * N * 2);

    const int total_warps = B * N * C;          // 153600
    const int threads = WARPS_PER_CTA * 32;
    const int blocks = (total_warps + WARPS_PER_CTA - 1) / WARPS_PER_CTA;

    glimpse_kernel<<<blocks, threads>>>(img, anc, out, out_xy);

    (void)n_in; (void)in_sizes; (void)out_size;
}

// round 15
// speedup vs baseline: 1.2539x; 1.0131x over previous
#include <cuda_runtime.h>
#include <cstdint>

// CornerProposal eval path on GB300 — R11: CTA-wide exact-packed bulk store.
//
// Math (exact, rel_err 5.28e-8 across R1-R3): anchor centers are
// integer-valued fp32; grid_sample(align_corners=False) sample points land at
// integer-0.5 => fx=fy=0.5 exactly => pure 2x2 box average, all taps
// in-bounds:
//   out[b,n,c,i,j] = 0.25*(I[y-1,x-1]+I[y-1,x]+I[y,x-1]+I[y,x])
//
// Roofline model (R3 post-mortem): kernel is L2-slot bound (~8.9KB of L2
// sector slots per task, ~1.36GB total ~= 113us at the ~6300 B/cyc LTS cap).
// R11 removes the last store-side slot waste: a CTA's 8 warps cover 8
// consecutive channels of one (b,n), so their 8x961=7688 outputs are one
// contiguous region at byte offset blockIdx*30752 — always 32B-aligned and a
// whole number of sectors. Stage all 8 channels contiguously in smem and emit
// ONE exactly sector-packed cp.async.bulk per CTA (no ragged STGs, no
// per-channel boundary splits, 1/8 the bulk ops).

static constexpr int B = 8;
static constexpr int N = 600;
static constexpr int C = 32;
static constexpr int H = 256;
static constexpr int W = 256;
static constexpr int G = 31;
static constexpr int GG = G * G;            // 961
static constexpr int WPC = 8;               // warps (=channels) per CTA
static constexpr int STAGE_F = WPC * GG;    // 7688 floats = 30752 B (mult of 32)

__global__ __launch_bounds__(WPC * 32)
void glimpse_kernel(const float* __restrict__ img,
                    const float* __restrict__ anc,
                    float* __restrict__ out,
                    float* __restrict__ out_xy)
{
    __shared__ __align__(32) float stage[STAGE_F];

    const int w     = threadIdx.x >> 5;
    const int lane  = threadIdx.x & 31;
    const int gwarp = blockIdx.x * WPC + w;

    // gwarp -> (bn, c); WPC divides C, so all 8 warps of a CTA share bn and
    // cover consecutive channels c0..c0+7.
    const int c  = gwarp & (C - 1);
    const int bn = gwarp >> 5;

    // anchor center = floor of (xmin, ymin); exact integer in fp32
    const float ax = __ldg(anc + (size_t)bn * 4 + 0);
    const float ay = __ldg(anc + (size_t)bn * 4 + 1);

    // fused anchor-xy copy (one warp per bn does it)
    if (c == 0 && lane < 2)
        out_xy[2 * bn + lane] = (lane == 0) ? ax : ay;

    const int cx = (int)floorf(ax);
    const int cy = (int)floorf(ay);
    const int b  = bn / N;

    // patch top-left (cy-16, cx-16); 32x32, guaranteed in-bounds
    const float* base = img + (((size_t)(b * C + c)) * H + (size_t)(cy - 16)) * W
                            + (cx - 16);

    // full 32x32 patch, one float per lane per row; unrolled for MLP
    // (proven load structure from R1/R3 — L2-hit heavy, sectors irreducible)
    float r[32];
    #pragma unroll
    for (int i = 0; i < 32; ++i)
        r[i] = __ldg(base + i * W + lane);

    // vertical pair sum per column, horizontal pair via shfl; stage flat:
    // stage[w*961 + i*31 + lane] — consecutive addresses per warp row,
    // conflict-free STS.
    #pragma unroll
    for (int i = 0; i < G; ++i) {
        const float s = r[i] + r[i + 1];
        const float t = s + __shfl_down_sync(0xffffffffu, s, 1);
        if (lane < G)
            stage[w * GG + i * G + lane] = 0.25f * t;
    }
    __syncthreads();

    // ONE exact-packed bulk store per CTA: 30752B at byte offset
    // blockIdx*30752 (32B-aligned, whole sectors, zero slot waste).
    if (threadIdx.x == 0) {
        asm volatile("fence.proxy.async.shared::cta;" ::: "memory");
        const uint32_t sa = (uint32_t)__cvta_generic_to_shared(stage);
        float* gptr = out + (size_t)blockIdx.x * STAGE_F;
        asm volatile("cp.async.bulk.global.shared::cta.bulk_group [%0], [%1], %2;"
                     :: "l"(gptr), "r"(sa), "r"((int)(STAGE_F * 4)) : "memory");
        asm volatile("cp.async.bulk.commit_group;" ::: "memory");
        // hold the CTA (and its smem) alive until the TMA engine has read smem
        asm volatile("cp.async.bulk.wait_group.read 0;" ::: "memory");
    }
}

extern "C" void kernel_launch(void* const* d_in, const int* in_sizes, int n_in,
                              void* d_out, int out_size)
{
    const float* img = (const float*)d_in[0];   // [B, C, H, W] fp32
    const float* anc = (const float*)d_in[1];   // [B, N, 4]   fp32
    float* out = (float*)d_out;

    // rois first, anchors(:, :, :2) appended
    float* out_xy = out + (out_size - B * N * 2);

    const int total_warps = B * N * C;          // 153600
    const int blocks = total_warps / WPC;       // 19200
    glimpse_kernel<<<blocks, WPC * 32>>>(img, anc, out, out_xy);

    (void)n_in; (void)in_sizes; (void)out_size;
}